// round 3
// baseline (speedup 1.0000x reference)
#include <cuda_runtime.h>
#include <math.h>

#define S_LEN 2048
#define BATCH 2
#define HID   1024
#define NH    16
#define HD    64
#define ROWS  (BATCH * S_LEN)   // 4096

// Scratch (device globals: no allocation allowed in kernel_launch)
__device__ float g_qkv[(size_t)ROWS * 3 * HID];  // [4096, 3072] raw QKV
__device__ float g_q[(size_t)ROWS * HID];        // [32 bh][2048 s][64 d]
__device__ float g_k[(size_t)ROWS * HID];
__device__ float g_v[(size_t)ROWS * HID];
__device__ float g_ao[(size_t)ROWS * HID];       // [4096, 1024] attn out (b,s,h,d)

// ---------------------------------------------------------------------------
// C[M,N] = A[M,K] * B[N,K]^T   (both row-major, K contiguous)
// 128x128 block tile, 16-wide K panel, 256 threads, 8x8 per-thread microtile
// ---------------------------------------------------------------------------
__global__ __launch_bounds__(256) void gemm_nt(
    const float* __restrict__ A, const float* __restrict__ B,
    float* __restrict__ C, int M, int N, int K) {
  __shared__ float As[16][128];
  __shared__ float Bs[16][128];
  const int t  = threadIdx.x;
  const int m0 = blockIdx.y * 128;
  const int n0 = blockIdx.x * 128;
  const int tx = t & 15;        // 0..15 -> col group
  const int ty = t >> 4;        // 0..15 -> row group
  const int lrow = t >> 2;      // 0..63
  const int lk   = (t & 3) << 2;

  const float* Ap = A + (size_t)(m0 + lrow) * K + lk;
  const float* Bp = B + (size_t)(n0 + lrow) * K + lk;

  float acc[8][8];
#pragma unroll
  for (int i = 0; i < 8; ++i)
#pragma unroll
    for (int j = 0; j < 8; ++j) acc[i][j] = 0.f;

  for (int k0 = 0; k0 < K; k0 += 16) {
    float4 a0 = *(const float4*)(Ap + k0);
    float4 a1 = *(const float4*)(Ap + (size_t)64 * K + k0);
    float4 b0 = *(const float4*)(Bp + k0);
    float4 b1 = *(const float4*)(Bp + (size_t)64 * K + k0);
    __syncthreads();
    As[lk + 0][lrow] = a0.x; As[lk + 1][lrow] = a0.y;
    As[lk + 2][lrow] = a0.z; As[lk + 3][lrow] = a0.w;
    As[lk + 0][lrow + 64] = a1.x; As[lk + 1][lrow + 64] = a1.y;
    As[lk + 2][lrow + 64] = a1.z; As[lk + 3][lrow + 64] = a1.w;
    Bs[lk + 0][lrow] = b0.x; Bs[lk + 1][lrow] = b0.y;
    Bs[lk + 2][lrow] = b0.z; Bs[lk + 3][lrow] = b0.w;
    Bs[lk + 0][lrow + 64] = b1.x; Bs[lk + 1][lrow + 64] = b1.y;
    Bs[lk + 2][lrow + 64] = b1.z; Bs[lk + 3][lrow + 64] = b1.w;
    __syncthreads();
#pragma unroll
    for (int kk = 0; kk < 16; ++kk) {
      float a[8], b[8];
      *(float4*)&a[0] = *(const float4*)&As[kk][ty * 8];
      *(float4*)&a[4] = *(const float4*)&As[kk][ty * 8 + 4];
      *(float4*)&b[0] = *(const float4*)&Bs[kk][tx * 8];
      *(float4*)&b[4] = *(const float4*)&Bs[kk][tx * 8 + 4];
#pragma unroll
      for (int i = 0; i < 8; ++i)
#pragma unroll
        for (int j = 0; j < 8; ++j)
          acc[i][j] = fmaf(a[i], b[j], acc[i][j]);
    }
  }
#pragma unroll
  for (int i = 0; i < 8; ++i) {
    float* cp = C + (size_t)(m0 + ty * 8 + i) * N + n0 + tx * 8;
    *(float4*)cp       = make_float4(acc[i][0], acc[i][1], acc[i][2], acc[i][3]);
    *(float4*)(cp + 4) = make_float4(acc[i][4], acc[i][5], acc[i][6], acc[i][7]);
  }
}

// ---------------------------------------------------------------------------
// RoPE on Q,K + split/transpose QKV[4096,3072] -> Q/K/V [bh][s][d]
// ---------------------------------------------------------------------------
__global__ __launch_bounds__(256) void rope_split_kernel(
    const float* __restrict__ qkv, float* __restrict__ Q,
    float* __restrict__ Kd, float* __restrict__ V) {
  __shared__ float inv_s[32];
  int t = threadIdx.x;
  if (t < 32) {
    float fwd = (float)pow(10000.0, (double)t / 32.0);
    inv_s[t] = 1.0f / fwd;
  }
  __syncthreads();

  int idx = blockIdx.x * 256 + t;    // 0 .. 4096*1024-1
  int r = idx >> 10;                 // row (b*2048+s)
  int c = idx & 1023;                // h*64 + d
  int h = c >> 6, d = c & 63;
  int b = r >> 11, s = r & 2047;

  const float* base = qkv + (size_t)r * 3072;
  float qv = base[c];
  float kv = base[1024 + c];
  float vv = base[2048 + c];

  int j = d & 31;
  float ang = inv_s[j] * (float)s;
  float cs = cosf(ang), sn = sinf(ang);

  float qp, kp;
  if (d < 32) {
    qp = -base[c + 32];
    kp = -base[1024 + c + 32];
  } else {
    qp = base[c - 32];
    kp = base[1024 + c - 32];
  }
  float qo = fmaf(qv, cs, qp * sn);
  float ko = fmaf(kv, cs, kp * sn);

  size_t o = ((size_t)(b * NH + h) * S_LEN + s) * HD + d;
  Q[o] = qo;
  Kd[o] = ko;
  V[o] = vv;
}

// ---------------------------------------------------------------------------
// Causal flash attention, fp32, balanced.
// Block p handles q-tiles p and 15-p sequentially -> every block does exactly
// 17 key-tile units of work (perfect static balance). 128 threads = 128 q-rows.
// ~184 regs -> 2 blocks/SM co-resident -> 2 warps/SMSP (FFMA rt=2 saturated).
// __expf (MUFU) instead of software expf; scale folded into q; rescale only
// when the running max actually changes.
// ---------------------------------------------------------------------------
__global__ __launch_bounds__(128) void attn_kernel(
    const float* __restrict__ Q, const float* __restrict__ K,
    const float* __restrict__ V, float* __restrict__ O) {
  __shared__ float Ks[64][64];
  __shared__ float Vs[64][64];
  const int tid  = threadIdx.x;
  const int pair = blockIdx.x;   // 0..7
  const int bh   = blockIdx.y;   // 0..31
  const int b = bh >> 4, h = bh & 15;

#pragma unroll 1
  for (int sel = 0; sel < 2; ++sel) {
    const int qt   = sel ? (15 - pair) : pair;
    const int qrow = qt * 128 + tid;

    const float* qptr = Q + ((size_t)bh * S_LEN + qrow) * HD;
    float4 qv[16], av[16];
#pragma unroll
    for (int i = 0; i < 16; ++i) {
      float4 qq = *(const float4*)(qptr + i * 4);
      qv[i] = make_float4(qq.x * 0.125f, qq.y * 0.125f, qq.z * 0.125f, qq.w * 0.125f);
      av[i] = make_float4(0.f, 0.f, 0.f, 0.f);
    }
    float mmax = -INFINITY, lsum = 0.f;
    const int kend = qt * 128 + 128;

    for (int kt = 0; kt < kend; kt += 64) {
      const float* kb = K + ((size_t)bh * S_LEN + kt) * HD;
      const float* vb = V + ((size_t)bh * S_LEN + kt) * HD;
      __syncthreads();
#pragma unroll
      for (int i = 0; i < 8; ++i) {
        int e  = tid + i * 128;
        int rr = e >> 4;
        int cc = (e & 15) << 2;
        *(float4*)&Ks[rr][cc] = *(const float4*)(kb + rr * HD + cc);
        *(float4*)&Vs[rr][cc] = *(const float4*)(vb + rr * HD + cc);
      }
      __syncthreads();

      const int jlim = min(64, qrow - kt + 1);  // keys [0, jlim) valid this tile
      for (int c0 = 0; c0 < 64; c0 += 16) {
        if (c0 >= jlim) break;
        float sc[16];
        float cmax = -INFINITY;
#pragma unroll 4
        for (int j = 0; j < 16; ++j) {
          float s0 = 0.f, s1 = 0.f, s2 = 0.f, s3 = 0.f;
#pragma unroll
          for (int i2 = 0; i2 < 16; ++i2) {
            float4 kk = *(const float4*)&Ks[c0 + j][i2 * 4];
            s0 = fmaf(qv[i2].x, kk.x, s0);
            s1 = fmaf(qv[i2].y, kk.y, s1);
            s2 = fmaf(qv[i2].z, kk.z, s2);
            s3 = fmaf(qv[i2].w, kk.w, s3);
          }
          float s = (s0 + s1) + (s2 + s3);   // scale already folded into q
          if (c0 + j >= jlim) s = -INFINITY;
          sc[j] = s;
          cmax  = fmaxf(cmax, s);
        }
        if (cmax > mmax) {
          float mnew = cmax;
          float corr = __expf(mmax - mnew);  // __expf(-inf)=0 handles 1st chunk
          lsum *= corr;
#pragma unroll
          for (int i = 0; i < 16; ++i) {
            av[i].x *= corr; av[i].y *= corr; av[i].z *= corr; av[i].w *= corr;
          }
          mmax = mnew;
        }
#pragma unroll 2
        for (int j = 0; j < 16; ++j) {
          float p = __expf(sc[j] - mmax);
          lsum += p;
#pragma unroll
          for (int i2 = 0; i2 < 16; ++i2) {
            float4 vv = *(const float4*)&Vs[c0 + j][i2 * 4];
            av[i2].x = fmaf(p, vv.x, av[i2].x);
            av[i2].y = fmaf(p, vv.y, av[i2].y);
            av[i2].z = fmaf(p, vv.z, av[i2].z);
            av[i2].w = fmaf(p, vv.w, av[i2].w);
          }
        }
      }
    }

    float rcp = 1.0f / lsum;
    float* op = O + (size_t)(b * S_LEN + qrow) * HID + h * HD;
#pragma unroll
    for (int i = 0; i < 16; ++i) {
      *(float4*)(op + i * 4) =
          make_float4(av[i].x * rcp, av[i].y * rcp, av[i].z * rcp, av[i].w * rcp);
    }
    __syncthreads();   // protect smem before next sel iteration re-stages
  }
}

// ---------------------------------------------------------------------------
extern "C" void kernel_launch(void* const* d_in, const int* in_sizes, int n_in,
                              void* d_out, int out_size) {
  const float* x     = (const float*)d_in[0];  // [2,2048,1024]
  const float* w_qkv = (const float*)d_in[1];  // [3072,1024]
  const float* w_o   = (const float*)d_in[2];  // [1024,1024]
  float* out = (float*)d_out;                  // [2,2048,1024]

  float *qkv, *q, *k, *v, *ao;
  cudaGetSymbolAddress((void**)&qkv, g_qkv);
  cudaGetSymbolAddress((void**)&q,   g_q);
  cudaGetSymbolAddress((void**)&k,   g_k);
  cudaGetSymbolAddress((void**)&v,   g_v);
  cudaGetSymbolAddress((void**)&ao,  g_ao);

  // 1) QKV = X @ Wqkv^T      [4096,3072]
  gemm_nt<<<dim3(3 * HID / 128, ROWS / 128), 256>>>(x, w_qkv, qkv, ROWS, 3 * HID, HID);
  // 2) RoPE + split into [bh][s][d]
  rope_split_kernel<<<(ROWS * HID) / 256, 256>>>(qkv, q, k, v);
  // 3) causal attention (balanced pair scheduling) -> [b,s,h,d]
  attn_kernel<<<dim3(8, BATCH * NH), 128>>>(q, k, v, ao);
  // 4) out = AO @ Wo^T       [4096,1024]
  gemm_nt<<<dim3(HID / 128, ROWS / 128), 256>>>(ao, w_o, out, ROWS, HID, HID);
}

// round 4
// speedup vs baseline: 1.0016x; 1.0016x over previous
#include <cuda_runtime.h>
#include <math.h>

#define S_LEN 2048
#define BATCH 2
#define HID   1024
#define NH    16
#define HD    64
#define ROWS  (BATCH * S_LEN)   // 4096

// Scratch (device globals: no allocation allowed in kernel_launch)
__device__ float g_qkv[(size_t)ROWS * 3 * HID];  // [4096, 3072] raw QKV
__device__ float g_q[(size_t)ROWS * HID];        // [32 bh][2048 s][64 d]
__device__ float g_k[(size_t)ROWS * HID];
__device__ float g_v[(size_t)ROWS * HID];
__device__ float g_ao[(size_t)ROWS * HID];       // [4096, 1024] attn out (b,s,h,d)

// ---------------------------------------------------------------------------
// C[M,N] = A[M,K] * B[N,K]^T   (both row-major, K contiguous)
// 128x128 block tile, 16-wide K panel, 256 threads, 8x8 per-thread microtile
// ---------------------------------------------------------------------------
__global__ __launch_bounds__(256) void gemm_nt(
    const float* __restrict__ A, const float* __restrict__ B,
    float* __restrict__ C, int M, int N, int K) {
  __shared__ float As[16][128];
  __shared__ float Bs[16][128];
  const int t  = threadIdx.x;
  const int m0 = blockIdx.y * 128;
  const int n0 = blockIdx.x * 128;
  const int tx = t & 15;        // 0..15 -> col group
  const int ty = t >> 4;        // 0..15 -> row group
  const int lrow = t >> 2;      // 0..63
  const int lk   = (t & 3) << 2;

  const float* Ap = A + (size_t)(m0 + lrow) * K + lk;
  const float* Bp = B + (size_t)(n0 + lrow) * K + lk;

  float acc[8][8];
#pragma unroll
  for (int i = 0; i < 8; ++i)
#pragma unroll
    for (int j = 0; j < 8; ++j) acc[i][j] = 0.f;

  for (int k0 = 0; k0 < K; k0 += 16) {
    float4 a0 = *(const float4*)(Ap + k0);
    float4 a1 = *(const float4*)(Ap + (size_t)64 * K + k0);
    float4 b0 = *(const float4*)(Bp + k0);
    float4 b1 = *(const float4*)(Bp + (size_t)64 * K + k0);
    __syncthreads();
    As[lk + 0][lrow] = a0.x; As[lk + 1][lrow] = a0.y;
    As[lk + 2][lrow] = a0.z; As[lk + 3][lrow] = a0.w;
    As[lk + 0][lrow + 64] = a1.x; As[lk + 1][lrow + 64] = a1.y;
    As[lk + 2][lrow + 64] = a1.z; As[lk + 3][lrow + 64] = a1.w;
    Bs[lk + 0][lrow] = b0.x; Bs[lk + 1][lrow] = b0.y;
    Bs[lk + 2][lrow] = b0.z; Bs[lk + 3][lrow] = b0.w;
    Bs[lk + 0][lrow + 64] = b1.x; Bs[lk + 1][lrow + 64] = b1.y;
    Bs[lk + 2][lrow + 64] = b1.z; Bs[lk + 3][lrow + 64] = b1.w;
    __syncthreads();
#pragma unroll
    for (int kk = 0; kk < 16; ++kk) {
      float a[8], b[8];
      *(float4*)&a[0] = *(const float4*)&As[kk][ty * 8];
      *(float4*)&a[4] = *(const float4*)&As[kk][ty * 8 + 4];
      *(float4*)&b[0] = *(const float4*)&Bs[kk][tx * 8];
      *(float4*)&b[4] = *(const float4*)&Bs[kk][tx * 8 + 4];
#pragma unroll
      for (int i = 0; i < 8; ++i)
#pragma unroll
        for (int j = 0; j < 8; ++j)
          acc[i][j] = fmaf(a[i], b[j], acc[i][j]);
    }
  }
#pragma unroll
  for (int i = 0; i < 8; ++i) {
    float* cp = C + (size_t)(m0 + ty * 8 + i) * N + n0 + tx * 8;
    *(float4*)cp       = make_float4(acc[i][0], acc[i][1], acc[i][2], acc[i][3]);
    *(float4*)(cp + 4) = make_float4(acc[i][4], acc[i][5], acc[i][6], acc[i][7]);
  }
}

// ---------------------------------------------------------------------------
// RoPE on Q,K + split/transpose QKV[4096,3072] -> Q/K/V [bh][s][d]
// ---------------------------------------------------------------------------
__global__ __launch_bounds__(256) void rope_split_kernel(
    const float* __restrict__ qkv, float* __restrict__ Q,
    float* __restrict__ Kd, float* __restrict__ V) {
  __shared__ float inv_s[32];
  int t = threadIdx.x;
  if (t < 32) {
    float fwd = (float)pow(10000.0, (double)t / 32.0);
    inv_s[t] = 1.0f / fwd;
  }
  __syncthreads();

  int idx = blockIdx.x * 256 + t;    // 0 .. 4096*1024-1
  int r = idx >> 10;                 // row (b*2048+s)
  int c = idx & 1023;                // h*64 + d
  int h = c >> 6, d = c & 63;
  int b = r >> 11, s = r & 2047;

  const float* base = qkv + (size_t)r * 3072;
  float qv = base[c];
  float kv = base[1024 + c];
  float vv = base[2048 + c];

  int j = d & 31;
  float ang = inv_s[j] * (float)s;
  float cs = cosf(ang), sn = sinf(ang);

  float qp, kp;
  if (d < 32) {
    qp = -base[c + 32];
    kp = -base[1024 + c + 32];
  } else {
    qp = base[c - 32];
    kp = base[1024 + c - 32];
  }
  float qo = fmaf(qv, cs, qp * sn);
  float ko = fmaf(kv, cs, kp * sn);

  size_t o = ((size_t)(b * NH + h) * S_LEN + s) * HD + d;
  Q[o] = qo;
  Kd[o] = ko;
  V[o] = vv;
}

// ---------------------------------------------------------------------------
// Causal flash attention, fp32, balanced.
// Block p handles q-tiles p and 15-p sequentially -> every block does exactly
// 17 key-tile units of work (perfect static balance). 128 threads = 128 q-rows.
// ~184 regs -> 2 blocks/SM co-resident -> 2 warps/SMSP (FFMA rt=2 saturated).
// __expf (MUFU) instead of software expf; scale folded into q; rescale only
// when the running max actually changes.
// ---------------------------------------------------------------------------
__global__ __launch_bounds__(128) void attn_kernel(
    const float* __restrict__ Q, const float* __restrict__ K,
    const float* __restrict__ V, float* __restrict__ O) {
  __shared__ float Ks[64][64];
  __shared__ float Vs[64][64];
  const int tid  = threadIdx.x;
  const int pair = blockIdx.x;   // 0..7
  const int bh   = blockIdx.y;   // 0..31
  const int b = bh >> 4, h = bh & 15;

#pragma unroll 1
  for (int sel = 0; sel < 2; ++sel) {
    const int qt   = sel ? (15 - pair) : pair;
    const int qrow = qt * 128 + tid;

    const float* qptr = Q + ((size_t)bh * S_LEN + qrow) * HD;
    float4 qv[16], av[16];
#pragma unroll
    for (int i = 0; i < 16; ++i) {
      float4 qq = *(const float4*)(qptr + i * 4);
      qv[i] = make_float4(qq.x * 0.125f, qq.y * 0.125f, qq.z * 0.125f, qq.w * 0.125f);
      av[i] = make_float4(0.f, 0.f, 0.f, 0.f);
    }
    float mmax = -INFINITY, lsum = 0.f;
    const int kend = qt * 128 + 128;

    for (int kt = 0; kt < kend; kt += 64) {
      const float* kb = K + ((size_t)bh * S_LEN + kt) * HD;
      const float* vb = V + ((size_t)bh * S_LEN + kt) * HD;
      __syncthreads();
#pragma unroll
      for (int i = 0; i < 8; ++i) {
        int e  = tid + i * 128;
        int rr = e >> 4;
        int cc = (e & 15) << 2;
        *(float4*)&Ks[rr][cc] = *(const float4*)(kb + rr * HD + cc);
        *(float4*)&Vs[rr][cc] = *(const float4*)(vb + rr * HD + cc);
      }
      __syncthreads();

      const int jlim = min(64, qrow - kt + 1);  // keys [0, jlim) valid this tile
      for (int c0 = 0; c0 < 64; c0 += 16) {
        if (c0 >= jlim) break;
        float sc[16];
        float cmax = -INFINITY;
#pragma unroll 4
        for (int j = 0; j < 16; ++j) {
          float s0 = 0.f, s1 = 0.f, s2 = 0.f, s3 = 0.f;
#pragma unroll
          for (int i2 = 0; i2 < 16; ++i2) {
            float4 kk = *(const float4*)&Ks[c0 + j][i2 * 4];
            s0 = fmaf(qv[i2].x, kk.x, s0);
            s1 = fmaf(qv[i2].y, kk.y, s1);
            s2 = fmaf(qv[i2].z, kk.z, s2);
            s3 = fmaf(qv[i2].w, kk.w, s3);
          }
          float s = (s0 + s1) + (s2 + s3);   // scale already folded into q
          if (c0 + j >= jlim) s = -INFINITY;
          sc[j] = s;
          cmax  = fmaxf(cmax, s);
        }
        if (cmax > mmax) {
          float mnew = cmax;
          float corr = __expf(mmax - mnew);  // __expf(-inf)=0 handles 1st chunk
          lsum *= corr;
#pragma unroll
          for (int i = 0; i < 16; ++i) {
            av[i].x *= corr; av[i].y *= corr; av[i].z *= corr; av[i].w *= corr;
          }
          mmax = mnew;
        }
#pragma unroll 2
        for (int j = 0; j < 16; ++j) {
          float p = __expf(sc[j] - mmax);
          lsum += p;
#pragma unroll
          for (int i2 = 0; i2 < 16; ++i2) {
            float4 vv = *(const float4*)&Vs[c0 + j][i2 * 4];
            av[i2].x = fmaf(p, vv.x, av[i2].x);
            av[i2].y = fmaf(p, vv.y, av[i2].y);
            av[i2].z = fmaf(p, vv.z, av[i2].z);
            av[i2].w = fmaf(p, vv.w, av[i2].w);
          }
        }
      }
    }

    float rcp = 1.0f / lsum;
    float* op = O + (size_t)(b * S_LEN + qrow) * HID + h * HD;
#pragma unroll
    for (int i = 0; i < 16; ++i) {
      *(float4*)(op + i * 4) =
          make_float4(av[i].x * rcp, av[i].y * rcp, av[i].z * rcp, av[i].w * rcp);
    }
    __syncthreads();   // protect smem before next sel iteration re-stages
  }
}

// ---------------------------------------------------------------------------
extern "C" void kernel_launch(void* const* d_in, const int* in_sizes, int n_in,
                              void* d_out, int out_size) {
  const float* x     = (const float*)d_in[0];  // [2,2048,1024]
  const float* w_qkv = (const float*)d_in[1];  // [3072,1024]
  const float* w_o   = (const float*)d_in[2];  // [1024,1024]
  float* out = (float*)d_out;                  // [2,2048,1024]

  float *qkv, *q, *k, *v, *ao;
  cudaGetSymbolAddress((void**)&qkv, g_qkv);
  cudaGetSymbolAddress((void**)&q,   g_q);
  cudaGetSymbolAddress((void**)&k,   g_k);
  cudaGetSymbolAddress((void**)&v,   g_v);
  cudaGetSymbolAddress((void**)&ao,  g_ao);

  // 1) QKV = X @ Wqkv^T      [4096,3072]
  gemm_nt<<<dim3(3 * HID / 128, ROWS / 128), 256>>>(x, w_qkv, qkv, ROWS, 3 * HID, HID);
  // 2) RoPE + split into [bh][s][d]
  rope_split_kernel<<<(ROWS * HID) / 256, 256>>>(qkv, q, k, v);
  // 3) causal attention (balanced pair scheduling) -> [b,s,h,d]
  attn_kernel<<<dim3(8, BATCH * NH), 128>>>(q, k, v, ao);
  // 4) out = AO @ Wo^T       [4096,1024]
  gemm_nt<<<dim3(HID / 128, ROWS / 128), 256>>>(ao, w_o, out, ROWS, HID, HID);
}